// round 12
// baseline (speedup 1.0000x reference)
#include <cuda_runtime.h>

#define BB 16
#define SS 4096
#define HH 1024

// scratch: per-segment partial dec_fea [4][B][H]
__device__ float g_part[4 * BB * HH];

__device__ __forceinline__ float tanh_fast(float x) {
    float y;
    asm("tanh.approx.f32 %0, %1;" : "=f"(y) : "f"(x));
    return y;
}

// streaming (evict-first) float4 load for zero-reuse tensors
__device__ __forceinline__ float4 ldcs4(const float4* p) {
    float4 r;
    asm("ld.global.cs.v4.f32 {%0,%1,%2,%3}, [%4];"
        : "=f"(r.x), "=f"(r.y), "=f"(r.z), "=f"(r.w) : "l"(p));
    return r;
}

__device__ __forceinline__ float warp_sum(float v) {
#pragma unroll
    for (int o = 16; o > 0; o >>= 1) v += __shfl_xor_sync(0xffffffffu, v, o);
    return v;
}

__device__ __forceinline__ float warp_max(float v) {
#pragma unroll
    for (int o = 16; o > 0; o >>= 1) v = fmaxf(v, __shfl_xor_sync(0xffffffffu, v, o));
    return v;
}

// ---------------------------------------------------------------------------
// K1: split-K decode projection. grid (128, 4).
// Also zeroes the scores region (for K2 atomics) and c_t (for K3 atomics).
// ---------------------------------------------------------------------------
__global__ void k_decproj(const float* __restrict__ s_t,
                          const float* __restrict__ W,
                          const float* __restrict__ bias,
                          float* __restrict__ out) {
    float* scores = out + BB * HH + 2 * BB * SS;
    {
        int gid = (blockIdx.x * 4 + blockIdx.y) * 256 + threadIdx.x;  // 0..131071
        if (gid < 65536) scores[gid] = 0.f;
        if (gid < BB * HH) out[gid] = 0.f;   // zero c_t
    }

    int warp = threadIdx.x >> 5, lane = threadIdx.x & 31;
    int h   = blockIdx.x * 8 + warp;
    int seg = blockIdx.y;
    int k0  = seg * 64;

    float acc[BB];
#pragma unroll
    for (int b = 0; b < BB; b++) acc[b] = 0.f;

    const float4* Wrow = reinterpret_cast<const float4*>(W + (size_t)h * HH);
#pragma unroll
    for (int it = 0; it < 2; it++) {
        int k4 = k0 + it * 32 + lane;
        float4 w = __ldg(Wrow + k4);
#pragma unroll
        for (int b = 0; b < BB; b++) {
            float4 s4 = __ldg(reinterpret_cast<const float4*>(s_t + b * HH) + k4);
            acc[b] += w.x * s4.x + w.y * s4.y + w.z * s4.z + w.w * s4.w;
        }
    }
    float bi = (seg == 0) ? __ldg(bias + h) : 0.f;
#pragma unroll
    for (int b = 0; b < BB; b++) {
        float r = warp_sum(acc[b]);
        if (lane == 0) g_part[(seg * BB + b) * HH + h] = r + bi;
    }
}

// ---------------------------------------------------------------------------
// K2: scores[b][s] += sum_{h in slice} tanh(ef + dec + cov*Wc) * v
// (R11 shape: flat 8-row .cs LDG batch, merged butterflies + REDG.)
// ---------------------------------------------------------------------------
#define SC_CHUNK 64

__device__ __forceinline__ void butterfly4_atomic(float a0, float a1, float a2,
                                                  float a3, int lane,
                                                  float* dst) {
    float x01 = (lane & 16) ? a1 : a0;
    float y01 = (lane & 16) ? a0 : a1;
    x01 += __shfl_xor_sync(0xffffffffu, y01, 16);
    float x23 = (lane & 16) ? a3 : a2;
    float y23 = (lane & 16) ? a2 : a3;
    x23 += __shfl_xor_sync(0xffffffffu, y23, 16);
    float m0 = (lane & 8) ? x23 : x01;
    float m1 = (lane & 8) ? x01 : x23;
    m0 += __shfl_xor_sync(0xffffffffu, m1, 8);
    m0 += __shfl_xor_sync(0xffffffffu, m0, 4);
    m0 += __shfl_xor_sync(0xffffffffu, m0, 2);
    m0 += __shfl_xor_sync(0xffffffffu, m0, 1);
    if ((lane & 7) == 0) {
        int r = ((lane >> 4) & 1) | ((lane >> 2) & 2);
        atomicAdd(dst + r, m0);
    }
}

__global__ void __launch_bounds__(128, 8) k_scores(const float* __restrict__ ef,
                                                   const float* __restrict__ cov,
                                                   const float* __restrict__ Wc,
                                                   const float* __restrict__ v,
                                                   float* __restrict__ scores) {
    int b  = blockIdx.y;
    int s0 = blockIdx.x * SC_CHUNK;
    int t  = blockIdx.z * 128 + threadIdx.x;
    int lane = threadIdx.x & 31;

    float4 p0 = __ldg(reinterpret_cast<const float4*>(g_part + (0 * BB + b) * HH) + t);
    float4 p1 = __ldg(reinterpret_cast<const float4*>(g_part + (1 * BB + b) * HH) + t);
    float4 p2 = __ldg(reinterpret_cast<const float4*>(g_part + (2 * BB + b) * HH) + t);
    float4 p3 = __ldg(reinterpret_cast<const float4*>(g_part + (3 * BB + b) * HH) + t);
    float4 d4;
    d4.x = (p0.x + p1.x) + (p2.x + p3.x);
    d4.y = (p0.y + p1.y) + (p2.y + p3.y);
    d4.z = (p0.z + p1.z) + (p2.z + p3.z);
    d4.w = (p0.w + p1.w) + (p2.w + p3.w);
    float4 w4 = __ldg(reinterpret_cast<const float4*>(Wc) + t);
    float4 v4 = __ldg(reinterpret_cast<const float4*>(v) + t);

    const float4* efb  = reinterpret_cast<const float4*>(ef + ((size_t)b * SS) * HH);
    const float4* cov4 = reinterpret_cast<const float4*>(cov + b * SS + s0);
    float* sc = scores + b * SS + s0;

#pragma unroll 1
    for (int g = 0; g < SC_CHUNK / 8; g++) {
        float4 f[8];
#pragma unroll
        for (int r = 0; r < 8; r++)
            f[r] = ldcs4(efb + (size_t)(s0 + g * 8 + r) * (HH / 4) + t);
        float4 c4a = __ldg(cov4 + g * 2);
        float4 c4b = __ldg(cov4 + g * 2 + 1);

        const float cr[8] = {c4a.x, c4a.y, c4a.z, c4a.w,
                             c4b.x, c4b.y, c4b.z, c4b.w};
        float acc[8];
#pragma unroll
        for (int r = 0; r < 8; r++) {
            float c = cr[r];
            float e0 = tanh_fast(f[r].x + fmaf(c, w4.x, d4.x));
            float e1 = tanh_fast(f[r].y + fmaf(c, w4.y, d4.y));
            float e2 = tanh_fast(f[r].z + fmaf(c, w4.z, d4.z));
            float e3 = tanh_fast(f[r].w + fmaf(c, w4.w, d4.w));
            acc[r] = fmaf(e0, v4.x, fmaf(e1, v4.y, fmaf(e2, v4.z, e3 * v4.w)));
        }
        butterfly4_atomic(acc[0], acc[1], acc[2], acc[3], lane, sc + g * 8);
        butterfly4_atomic(acc[4], acc[5], acc[6], acc[7], lane, sc + g * 8 + 4);
    }
}

// ---------------------------------------------------------------------------
// K3: fused softmax + context.
// Each block recomputes its batch's softmax stats from scores (L2-hot),
// materializes attn for its 64-row chunk in smem, then streams eo.
// Blocks with x==0 additionally write the attn output regions (z selects
// attn1 vs attn2). c_t accumulated via REDG atomics (zeroed in K1).
// ---------------------------------------------------------------------------
#define K4_CHUNK 64
__global__ void __launch_bounds__(128, 8) k_context(const float* __restrict__ eo,
                                                    const float* __restrict__ mask,
                                                    float* __restrict__ out) {
    int b   = blockIdx.y;
    int s0  = blockIdx.x * K4_CHUNK;
    int t   = blockIdx.z * 128 + threadIdx.x;
    int tid = threadIdx.x;
    int warp = tid >> 5, lane = tid & 31;

    const float4* scb = reinterpret_cast<const float4*>(out + BB * HH + 2 * BB * SS + b * SS);
    const float4* mb  = reinterpret_cast<const float4*>(mask + b * SS);

    __shared__ float red[8];
    __shared__ float attn_sm[K4_CHUNK];

    // ---- softmax stats over the batch's 4096 scores ----
    float4 sv[8];
#pragma unroll
    for (int k = 0; k < 8; k++) sv[k] = __ldg(scb + tid + k * 128);

    float mx = -3.402823466e+38f;
#pragma unroll
    for (int k = 0; k < 8; k++)
        mx = fmaxf(mx, fmaxf(fmaxf(sv[k].x, sv[k].y), fmaxf(sv[k].z, sv[k].w)));
    mx = warp_max(mx);
    if (lane == 0) red[warp] = mx;
    __syncthreads();
    if (tid == 0) red[0] = fmaxf(fmaxf(red[0], red[1]), fmaxf(red[2], red[3]));
    __syncthreads();
    mx = red[0];
    __syncthreads();

    float lsum = 0.f;
#pragma unroll
    for (int k = 0; k < 8; k++) {
        sv[k].x = __expf(sv[k].x - mx); sv[k].y = __expf(sv[k].y - mx);
        sv[k].z = __expf(sv[k].z - mx); sv[k].w = __expf(sv[k].w - mx);
        lsum += (sv[k].x + sv[k].y) + (sv[k].z + sv[k].w);
    }
    lsum = warp_sum(lsum);
    if (lane == 0) red[warp] = lsum;
    __syncthreads();
    if (tid == 0) red[0] = (red[0] + red[1]) + (red[2] + red[3]);
    __syncthreads();
    float inv = 1.f / red[0];
    __syncthreads();

    float lms = 0.f;
#pragma unroll
    for (int k = 0; k < 8; k++) {
        float4 m4 = __ldg(mb + tid + k * 128);
        lms += (sv[k].x * m4.x + sv[k].y * m4.y) + (sv[k].z * m4.z + sv[k].w * m4.w);
    }
    lms = warp_sum(lms);
    if (lane == 0) red[warp] = lms;
    __syncthreads();
    if (tid == 0) red[0] = (red[0] + red[1]) + (red[2] + red[3]);
    __syncthreads();
    float inv2 = 1.f / (red[0] * inv + 1e-20f);
    float scale = inv * inv2;

    // ---- blocks x==0 write the attn output regions ----
    if (blockIdx.x == 0) {
        float4* dst = reinterpret_cast<float4*>(out + BB * HH + blockIdx.z * BB * SS + b * SS);
#pragma unroll
        for (int k = 0; k < 8; k++) {
            float4 m4 = __ldg(mb + tid + k * 128);
            float4 a;
            a.x = sv[k].x * m4.x * scale; a.y = sv[k].y * m4.y * scale;
            a.z = sv[k].z * m4.z * scale; a.w = sv[k].w * m4.w * scale;
            dst[tid + k * 128] = a;
        }
    }

    // ---- materialize this chunk's 64 attn values in smem ----
    if (tid < K4_CHUNK / 4) {
        int i4 = s0 / 4 + tid;
        float4 s4 = __ldg(scb + i4);
        float4 m4 = __ldg(mb + i4);
        float4 a;
        a.x = __expf(s4.x - mx) * m4.x * scale;
        a.y = __expf(s4.y - mx) * m4.y * scale;
        a.z = __expf(s4.z - mx) * m4.z * scale;
        a.w = __expf(s4.w - mx) * m4.w * scale;
        reinterpret_cast<float4*>(attn_sm)[tid] = a;
    }
    __syncthreads();

    // ---- stream encoder_outputs ----
    const float4* eob = reinterpret_cast<const float4*>(eo + ((size_t)b * SS) * HH);
    float4 acc = make_float4(0.f, 0.f, 0.f, 0.f);
#pragma unroll 4
    for (int i = 0; i < K4_CHUNK; i++) {
        float a  = attn_sm[i];
        float4 e = ldcs4(eob + (size_t)(s0 + i) * (HH / 4) + t);
        acc.x += a * e.x; acc.y += a * e.y;
        acc.z += a * e.z; acc.w += a * e.w;
    }
    float* ct = out + b * HH + t * 4;
    atomicAdd(ct + 0, acc.x);
    atomicAdd(ct + 1, acc.y);
    atomicAdd(ct + 2, acc.z);
    atomicAdd(ct + 3, acc.w);
}

// ---------------------------------------------------------------------------
extern "C" void kernel_launch(void* const* d_in, const int* in_sizes, int n_in,
                              void* d_out, int out_size) {
    const float* s_t_hat = (const float*)d_in[0];
    const float* enc_out = (const float*)d_in[1];
    const float* enc_fea = (const float*)d_in[2];
    const float* mask    = (const float*)d_in[3];
    const float* cov     = (const float*)d_in[4];
    const float* W_dec   = (const float*)d_in[5];
    const float* b_dec   = (const float*)d_in[6];
    const float* W_c     = (const float*)d_in[7];
    const float* v       = (const float*)d_in[8];
    float* out = (float*)d_out;

    float* scores = out + BB * HH + 2 * BB * SS;

    k_decproj<<<dim3(128, 4), 256>>>(s_t_hat, W_dec, b_dec, out);
    k_scores<<<dim3(SS / SC_CHUNK, BB, 2), 128>>>(enc_fea, cov, W_c, v, scores);
    k_context<<<dim3(SS / K4_CHUNK, BB, 2), 128>>>(enc_out, mask, out);
}

// round 13
// speedup vs baseline: 1.0073x; 1.0073x over previous
#include <cuda_runtime.h>

#define BB 16
#define SS 4096
#define HH 1024

// scratch: per-segment partial dec_fea [8][B][H]
__device__ float g_part[8 * BB * HH];

__device__ __forceinline__ float tanh_fast(float x) {
    float y;
    asm("tanh.approx.f32 %0, %1;" : "=f"(y) : "f"(x));
    return y;
}

// streaming (evict-first) float4 load for zero-reuse tensors
__device__ __forceinline__ float4 ldcs4(const float4* p) {
    float4 r;
    asm("ld.global.cs.v4.f32 {%0,%1,%2,%3}, [%4];"
        : "=f"(r.x), "=f"(r.y), "=f"(r.z), "=f"(r.w) : "l"(p));
    return r;
}

__device__ __forceinline__ float warp_sum(float v) {
#pragma unroll
    for (int o = 16; o > 0; o >>= 1) v += __shfl_xor_sync(0xffffffffu, v, o);
    return v;
}

__device__ __forceinline__ float warp_max(float v) {
#pragma unroll
    for (int o = 16; o > 0; o >>= 1) v = fmaxf(v, __shfl_xor_sync(0xffffffffu, v, o));
    return v;
}

// ---------------------------------------------------------------------------
// K1: split-K decode projection, 8 segments of 128 floats.
// grid (128, 8) = 1024 blocks (6.9/SM). Each warp owns one (h, seg): lane l
// holds float4 #l of the segment -> 1 w load + 16 batch loads, ALL
// independent; 16 warp_sums -> g_part[seg][b][h]. Bias folded into seg 0.
// Also zeroes the scores region for K2's atomics.
// ---------------------------------------------------------------------------
__global__ void k_decproj(const float* __restrict__ s_t,
                          const float* __restrict__ W,
                          const float* __restrict__ bias,
                          float* __restrict__ scores) {
    int gid = (blockIdx.x * 8 + blockIdx.y) * 256 + threadIdx.x;
    if (gid < 65536) scores[gid] = 0.f;

    int warp = threadIdx.x >> 5, lane = threadIdx.x & 31;
    int h   = blockIdx.x * 8 + warp;
    int seg = blockIdx.y;
    int k4  = seg * 32 + lane;   // float4 index within the 1024-float row

    float4 w = __ldg(reinterpret_cast<const float4*>(W + (size_t)h * HH) + k4);

    float acc[BB];
#pragma unroll
    for (int b = 0; b < BB; b++) {
        float4 s4 = __ldg(reinterpret_cast<const float4*>(s_t + b * HH) + k4);
        acc[b] = (w.x * s4.x + w.y * s4.y) + (w.z * s4.z + w.w * s4.w);
    }
    float bi = (seg == 0) ? __ldg(bias + h) : 0.f;
#pragma unroll
    for (int b = 0; b < BB; b++) {
        float r = warp_sum(acc[b]);
        if (lane == 0) g_part[(seg * BB + b) * HH + h] = r + bi;
    }
}

// ---------------------------------------------------------------------------
// K2: scores[b][s] += sum_{h in slice} tanh(ef + dec + cov*Wc) * v
// R11 shape: flat 8-row .cs LDG batch (MLP 8), merged butterflies + REDG.
// dec gathered from 8 split-K partials.
// ---------------------------------------------------------------------------
#define SC_CHUNK 64

__device__ __forceinline__ void butterfly4_atomic(float a0, float a1, float a2,
                                                  float a3, int lane,
                                                  float* dst) {
    float x01 = (lane & 16) ? a1 : a0;
    float y01 = (lane & 16) ? a0 : a1;
    x01 += __shfl_xor_sync(0xffffffffu, y01, 16);
    float x23 = (lane & 16) ? a3 : a2;
    float y23 = (lane & 16) ? a2 : a3;
    x23 += __shfl_xor_sync(0xffffffffu, y23, 16);
    float m0 = (lane & 8) ? x23 : x01;
    float m1 = (lane & 8) ? x01 : x23;
    m0 += __shfl_xor_sync(0xffffffffu, m1, 8);
    m0 += __shfl_xor_sync(0xffffffffu, m0, 4);
    m0 += __shfl_xor_sync(0xffffffffu, m0, 2);
    m0 += __shfl_xor_sync(0xffffffffu, m0, 1);
    if ((lane & 7) == 0) {
        int r = ((lane >> 4) & 1) | ((lane >> 2) & 2);
        atomicAdd(dst + r, m0);
    }
}

__global__ void __launch_bounds__(128, 8) k_scores(const float* __restrict__ ef,
                                                   const float* __restrict__ cov,
                                                   const float* __restrict__ Wc,
                                                   const float* __restrict__ v,
                                                   float* __restrict__ scores) {
    int b  = blockIdx.y;
    int s0 = blockIdx.x * SC_CHUNK;
    int t  = blockIdx.z * 128 + threadIdx.x;   // float4 index within h row
    int lane = threadIdx.x & 31;

    // gather dec from 8 split-K partials
    float4 d4 = make_float4(0.f, 0.f, 0.f, 0.f);
#pragma unroll
    for (int seg = 0; seg < 8; seg++) {
        float4 p = __ldg(reinterpret_cast<const float4*>(g_part + (seg * BB + b) * HH) + t);
        d4.x += p.x; d4.y += p.y; d4.z += p.z; d4.w += p.w;
    }
    float4 w4 = __ldg(reinterpret_cast<const float4*>(Wc) + t);
    float4 v4 = __ldg(reinterpret_cast<const float4*>(v) + t);

    const float4* efb  = reinterpret_cast<const float4*>(ef + ((size_t)b * SS) * HH);
    const float4* cov4 = reinterpret_cast<const float4*>(cov + b * SS + s0);
    float* sc = scores + b * SS + s0;

#pragma unroll 1
    for (int g = 0; g < SC_CHUNK / 8; g++) {
        // ---- load phase: 8 independent streaming LDG.128 + 2 cov loads ----
        float4 f[8];
#pragma unroll
        for (int r = 0; r < 8; r++)
            f[r] = ldcs4(efb + (size_t)(s0 + g * 8 + r) * (HH / 4) + t);
        float4 c4a = __ldg(cov4 + g * 2);
        float4 c4b = __ldg(cov4 + g * 2 + 1);

        // ---- compute phase ----
        const float cr[8] = {c4a.x, c4a.y, c4a.z, c4a.w,
                             c4b.x, c4b.y, c4b.z, c4b.w};
        float acc[8];
#pragma unroll
        for (int r = 0; r < 8; r++) {
            float c = cr[r];
            float e0 = tanh_fast(f[r].x + fmaf(c, w4.x, d4.x));
            float e1 = tanh_fast(f[r].y + fmaf(c, w4.y, d4.y));
            float e2 = tanh_fast(f[r].z + fmaf(c, w4.z, d4.z));
            float e3 = tanh_fast(f[r].w + fmaf(c, w4.w, d4.w));
            acc[r] = fmaf(e0, v4.x, fmaf(e1, v4.y, fmaf(e2, v4.z, e3 * v4.w)));
        }
        butterfly4_atomic(acc[0], acc[1], acc[2], acc[3], lane, sc + g * 8);
        butterfly4_atomic(acc[4], acc[5], acc[6], acc[7], lane, sc + g * 8 + 4);
    }
}

// ---------------------------------------------------------------------------
// K3: masked softmax + renorm; writes attn twice; zeroes c_t.
// ---------------------------------------------------------------------------
__global__ void k_softmax(const float* __restrict__ mask, float* __restrict__ out) {
    int b   = blockIdx.x;
    int tid = threadIdx.x;
    const float4* sc = reinterpret_cast<const float4*>(out + BB * HH + 2 * BB * SS + b * SS);
    float4* attn1 = reinterpret_cast<float4*>(out + BB * HH + b * SS);
    float4* attn2 = reinterpret_cast<float4*>(out + BB * HH + BB * SS + b * SS);
    const float4* m4p = reinterpret_cast<const float4*>(mask + b * SS);

    __shared__ float red[32];
    int warp = tid >> 5, lane = tid & 31;

    float4 x = sc[tid];

    float mx = fmaxf(fmaxf(x.x, x.y), fmaxf(x.z, x.w));
    mx = warp_max(mx);
    if (lane == 0) red[warp] = mx;
    __syncthreads();
    if (tid < 32) {
        float t = red[tid];
        t = warp_max(t);
        if (tid == 0) red[0] = t;
    }
    __syncthreads();
    mx = red[0];
    __syncthreads();

    float4 p;
    p.x = __expf(x.x - mx); p.y = __expf(x.y - mx);
    p.z = __expf(x.z - mx); p.w = __expf(x.w - mx);

    float sm = p.x + p.y + p.z + p.w;
    sm = warp_sum(sm);
    if (lane == 0) red[warp] = sm;
    __syncthreads();
    if (tid < 32) {
        float t = red[tid];
        t = warp_sum(t);
        if (tid == 0) red[0] = t;
    }
    __syncthreads();
    float denom = red[0];
    __syncthreads();

    float4 m = m4p[tid];
    float4 a0;
    float inv = 1.f / denom;
    a0.x = p.x * inv * m.x; a0.y = p.y * inv * m.y;
    a0.z = p.z * inv * m.z; a0.w = p.w * inv * m.w;

    float s2 = a0.x + a0.y + a0.z + a0.w;
    s2 = warp_sum(s2);
    if (lane == 0) red[warp] = s2;
    __syncthreads();
    if (tid < 32) {
        float t = red[tid];
        t = warp_sum(t);
        if (tid == 0) red[0] = t;
    }
    __syncthreads();
    float inv2 = 1.f / (red[0] + 1e-20f);

    float4 a;
    a.x = a0.x * inv2; a.y = a0.y * inv2; a.z = a0.z * inv2; a.w = a0.w * inv2;
    attn1[tid] = a;
    attn2[tid] = a;

    out[b * HH + tid] = 0.f;
}

// ---------------------------------------------------------------------------
// K4: c_t[b][h] += sum_{s in chunk} attn[b,s] * eo[b,s,h]
// Static grid; eo streamed with ld.global.cs.
// ---------------------------------------------------------------------------
#define K4_CHUNK 64
__global__ void __launch_bounds__(128) k_context(const float* __restrict__ eo,
                                                 float* __restrict__ out) {
    int b  = blockIdx.y;
    int s0 = blockIdx.x * K4_CHUNK;
    int t  = blockIdx.z * 128 + threadIdx.x;
    const float* attn = out + BB * HH + b * SS;
    const float4* eob = reinterpret_cast<const float4*>(eo + ((size_t)b * SS) * HH);

    float4 acc = make_float4(0.f, 0.f, 0.f, 0.f);
#pragma unroll 4
    for (int i = 0; i < K4_CHUNK; i++) {
        int s = s0 + i;
        float a  = __ldg(attn + s);
        float4 e = ldcs4(eob + (size_t)s * (HH / 4) + t);
        acc.x += a * e.x; acc.y += a * e.y;
        acc.z += a * e.z; acc.w += a * e.w;
    }
    float* ct = out + b * HH + t * 4;
    atomicAdd(ct + 0, acc.x);
    atomicAdd(ct + 1, acc.y);
    atomicAdd(ct + 2, acc.z);
    atomicAdd(ct + 3, acc.w);
}

// ---------------------------------------------------------------------------
extern "C" void kernel_launch(void* const* d_in, const int* in_sizes, int n_in,
                              void* d_out, int out_size) {
    const float* s_t_hat = (const float*)d_in[0];
    const float* enc_out = (const float*)d_in[1];
    const float* enc_fea = (const float*)d_in[2];
    const float* mask    = (const float*)d_in[3];
    const float* cov     = (const float*)d_in[4];
    const float* W_dec   = (const float*)d_in[5];
    const float* b_dec   = (const float*)d_in[6];
    const float* W_c     = (const float*)d_in[7];
    const float* v       = (const float*)d_in[8];
    float* out = (float*)d_out;

    float* scores = out + BB * HH + 2 * BB * SS;

    k_decproj<<<dim3(128, 8), 256>>>(s_t_hat, W_dec, b_dec, scores);
    k_scores<<<dim3(SS / SC_CHUNK, BB, 2), 128>>>(enc_fea, cov, W_c, v, scores);
    k_softmax<<<BB, 1024>>>(mask, out);
    k_context<<<dim3(SS / K4_CHUNK, BB, 2), 128>>>(enc_out, out);
}

// round 14
// speedup vs baseline: 1.0256x; 1.0182x over previous
#include <cuda_runtime.h>

#define BB 16
#define SS 4096
#define HH 1024

// scratch: per-segment partial dec_fea [4][B][H]
__device__ float g_part[4 * BB * HH];

__device__ __forceinline__ float tanh_fast(float x) {
    float y;
    asm("tanh.approx.f32 %0, %1;" : "=f"(y) : "f"(x));
    return y;
}

// streaming (evict-first) float4 load for zero-reuse tensors
__device__ __forceinline__ float4 ldcs4(const float4* p) {
    float4 r;
    asm("ld.global.cs.v4.f32 {%0,%1,%2,%3}, [%4];"
        : "=f"(r.x), "=f"(r.y), "=f"(r.z), "=f"(r.w) : "l"(p));
    return r;
}

__device__ __forceinline__ float warp_sum(float v) {
#pragma unroll
    for (int o = 16; o > 0; o >>= 1) v += __shfl_xor_sync(0xffffffffu, v, o);
    return v;
}

__device__ __forceinline__ float warp_max(float v) {
#pragma unroll
    for (int o = 16; o > 0; o >>= 1) v = fmaxf(v, __shfl_xor_sync(0xffffffffu, v, o));
    return v;
}

// ---------------------------------------------------------------------------
// K1: split-K decode projection, 4 segments of 256 floats.
// grid (256, 4) x 128 thr = 1024 blocks. Warp = (h, seg): lane owns 2 float4
// of the segment; 16 batch accumulators reduced by a merged butterfly-16
// (5 SHFL total instead of 16 warp_sums = 80 SHFL). Even lane l writes
// batch (l>>1)&15. Bias folded into segment 0. Also zeroes scores.
// ---------------------------------------------------------------------------
__global__ void k_decproj(const float* __restrict__ s_t,
                          const float* __restrict__ W,
                          const float* __restrict__ bias,
                          float* __restrict__ scores) {
    int gid = (blockIdx.x * 4 + blockIdx.y) * 128 + threadIdx.x;
    if (gid < 65536) scores[gid] = 0.f;

    int warp = threadIdx.x >> 5, lane = threadIdx.x & 31;
    int h   = blockIdx.x * 4 + warp;
    int seg = blockIdx.y;
    int k4a = seg * 64 + lane;        // first float4 of this lane
    int k4b = k4a + 32;               // second float4

    const float4* Wrow = reinterpret_cast<const float4*>(W + (size_t)h * HH);
    float4 wa = __ldg(Wrow + k4a);
    float4 wb = __ldg(Wrow + k4b);

    float r[16];
#pragma unroll
    for (int b = 0; b < BB; b++) {
        const float4* sb = reinterpret_cast<const float4*>(s_t + b * HH);
        float4 sa = __ldg(sb + k4a);
        float4 s2 = __ldg(sb + k4b);
        r[b] = (wa.x * sa.x + wa.y * sa.y) + (wa.z * sa.z + wa.w * sa.w)
             + (wb.x * s2.x + wb.y * s2.y) + (wb.z * s2.z + wb.w * s2.w);
    }

    // merged butterfly-16: 5 SHFL total; result at even lanes,
    // batch index = (lane>>1) & 15
    float m8[8];
#pragma unroll
    for (int i = 0; i < 8; i++) {
        bool hi = (lane & 16) != 0;
        float keep = hi ? r[i + 8] : r[i];
        float send = hi ? r[i] : r[i + 8];
        m8[i] = keep + __shfl_xor_sync(0xffffffffu, send, 16);
    }
    float m4[4];
#pragma unroll
    for (int i = 0; i < 4; i++) {
        bool hi = (lane & 8) != 0;
        float keep = hi ? m8[i + 4] : m8[i];
        float send = hi ? m8[i] : m8[i + 4];
        m4[i] = keep + __shfl_xor_sync(0xffffffffu, send, 8);
    }
    float m2[2];
#pragma unroll
    for (int i = 0; i < 2; i++) {
        bool hi = (lane & 4) != 0;
        float keep = hi ? m4[i + 2] : m4[i];
        float send = hi ? m4[i] : m4[i + 2];
        m2[i] = keep + __shfl_xor_sync(0xffffffffu, send, 4);
    }
    float m1;
    {
        bool hi = (lane & 2) != 0;
        float keep = hi ? m2[1] : m2[0];
        float send = hi ? m2[0] : m2[1];
        m1 = keep + __shfl_xor_sync(0xffffffffu, send, 2);
    }
    m1 += __shfl_xor_sync(0xffffffffu, m1, 1);

    if ((lane & 1) == 0) {
        int b = (lane >> 1) & 15;
        float bi = (seg == 0) ? __ldg(bias + h) : 0.f;
        g_part[(seg * BB + b) * HH + h] = m1 + bi;
    }
}

// ---------------------------------------------------------------------------
// K2: scores[b][s] += sum_{h in slice} tanh(ef + dec + cov*Wc) * v
// R11 shape: flat 8-row .cs LDG batch (MLP 8), merged butterflies + REDG.
// ---------------------------------------------------------------------------
#define SC_CHUNK 64

__device__ __forceinline__ void butterfly4_atomic(float a0, float a1, float a2,
                                                  float a3, int lane,
                                                  float* dst) {
    float x01 = (lane & 16) ? a1 : a0;
    float y01 = (lane & 16) ? a0 : a1;
    x01 += __shfl_xor_sync(0xffffffffu, y01, 16);
    float x23 = (lane & 16) ? a3 : a2;
    float y23 = (lane & 16) ? a2 : a3;
    x23 += __shfl_xor_sync(0xffffffffu, y23, 16);
    float m0 = (lane & 8) ? x23 : x01;
    float m1 = (lane & 8) ? x01 : x23;
    m0 += __shfl_xor_sync(0xffffffffu, m1, 8);
    m0 += __shfl_xor_sync(0xffffffffu, m0, 4);
    m0 += __shfl_xor_sync(0xffffffffu, m0, 2);
    m0 += __shfl_xor_sync(0xffffffffu, m0, 1);
    if ((lane & 7) == 0) {
        int r = ((lane >> 4) & 1) | ((lane >> 2) & 2);
        atomicAdd(dst + r, m0);
    }
}

__global__ void __launch_bounds__(128, 8) k_scores(const float* __restrict__ ef,
                                                   const float* __restrict__ cov,
                                                   const float* __restrict__ Wc,
                                                   const float* __restrict__ v,
                                                   float* __restrict__ scores) {
    int b  = blockIdx.y;
    int s0 = blockIdx.x * SC_CHUNK;
    int t  = blockIdx.z * 128 + threadIdx.x;
    int lane = threadIdx.x & 31;

    float4 p0 = __ldg(reinterpret_cast<const float4*>(g_part + (0 * BB + b) * HH) + t);
    float4 p1 = __ldg(reinterpret_cast<const float4*>(g_part + (1 * BB + b) * HH) + t);
    float4 p2 = __ldg(reinterpret_cast<const float4*>(g_part + (2 * BB + b) * HH) + t);
    float4 p3 = __ldg(reinterpret_cast<const float4*>(g_part + (3 * BB + b) * HH) + t);
    float4 d4;
    d4.x = (p0.x + p1.x) + (p2.x + p3.x);
    d4.y = (p0.y + p1.y) + (p2.y + p3.y);
    d4.z = (p0.z + p1.z) + (p2.z + p3.z);
    d4.w = (p0.w + p1.w) + (p2.w + p3.w);
    float4 w4 = __ldg(reinterpret_cast<const float4*>(Wc) + t);
    float4 v4 = __ldg(reinterpret_cast<const float4*>(v) + t);

    const float4* efb  = reinterpret_cast<const float4*>(ef + ((size_t)b * SS) * HH);
    const float4* cov4 = reinterpret_cast<const float4*>(cov + b * SS + s0);
    float* sc = scores + b * SS + s0;

#pragma unroll 1
    for (int g = 0; g < SC_CHUNK / 8; g++) {
        float4 f[8];
#pragma unroll
        for (int r = 0; r < 8; r++)
            f[r] = ldcs4(efb + (size_t)(s0 + g * 8 + r) * (HH / 4) + t);
        float4 c4a = __ldg(cov4 + g * 2);
        float4 c4b = __ldg(cov4 + g * 2 + 1);

        const float cr[8] = {c4a.x, c4a.y, c4a.z, c4a.w,
                             c4b.x, c4b.y, c4b.z, c4b.w};
        float acc[8];
#pragma unroll
        for (int r = 0; r < 8; r++) {
            float c = cr[r];
            float e0 = tanh_fast(f[r].x + fmaf(c, w4.x, d4.x));
            float e1 = tanh_fast(f[r].y + fmaf(c, w4.y, d4.y));
            float e2 = tanh_fast(f[r].z + fmaf(c, w4.z, d4.z));
            float e3 = tanh_fast(f[r].w + fmaf(c, w4.w, d4.w));
            acc[r] = fmaf(e0, v4.x, fmaf(e1, v4.y, fmaf(e2, v4.z, e3 * v4.w)));
        }
        butterfly4_atomic(acc[0], acc[1], acc[2], acc[3], lane, sc + g * 8);
        butterfly4_atomic(acc[4], acc[5], acc[6], acc[7], lane, sc + g * 8 + 4);
    }
}

// ---------------------------------------------------------------------------
// K3: masked softmax + renorm; writes attn twice; zeroes c_t.
// ---------------------------------------------------------------------------
__global__ void k_softmax(const float* __restrict__ mask, float* __restrict__ out) {
    int b   = blockIdx.x;
    int tid = threadIdx.x;
    const float4* sc = reinterpret_cast<const float4*>(out + BB * HH + 2 * BB * SS + b * SS);
    float4* attn1 = reinterpret_cast<float4*>(out + BB * HH + b * SS);
    float4* attn2 = reinterpret_cast<float4*>(out + BB * HH + BB * SS + b * SS);
    const float4* m4p = reinterpret_cast<const float4*>(mask + b * SS);

    __shared__ float red[32];
    int warp = tid >> 5, lane = tid & 31;

    float4 x = sc[tid];

    float mx = fmaxf(fmaxf(x.x, x.y), fmaxf(x.z, x.w));
    mx = warp_max(mx);
    if (lane == 0) red[warp] = mx;
    __syncthreads();
    if (tid < 32) {
        float t = red[tid];
        t = warp_max(t);
        if (tid == 0) red[0] = t;
    }
    __syncthreads();
    mx = red[0];
    __syncthreads();

    float4 p;
    p.x = __expf(x.x - mx); p.y = __expf(x.y - mx);
    p.z = __expf(x.z - mx); p.w = __expf(x.w - mx);

    float sm = p.x + p.y + p.z + p.w;
    sm = warp_sum(sm);
    if (lane == 0) red[warp] = sm;
    __syncthreads();
    if (tid < 32) {
        float t = red[tid];
        t = warp_sum(t);
        if (tid == 0) red[0] = t;
    }
    __syncthreads();
    float denom = red[0];
    __syncthreads();

    float4 m = m4p[tid];
    float4 a0;
    float inv = 1.f / denom;
    a0.x = p.x * inv * m.x; a0.y = p.y * inv * m.y;
    a0.z = p.z * inv * m.z; a0.w = p.w * inv * m.w;

    float s2 = a0.x + a0.y + a0.z + a0.w;
    s2 = warp_sum(s2);
    if (lane == 0) red[warp] = s2;
    __syncthreads();
    if (tid < 32) {
        float t = red[tid];
        t = warp_sum(t);
        if (tid == 0) red[0] = t;
    }
    __syncthreads();
    float inv2 = 1.f / (red[0] + 1e-20f);

    float4 a;
    a.x = a0.x * inv2; a.y = a0.y * inv2; a.z = a0.z * inv2; a.w = a0.w * inv2;
    attn1[tid] = a;
    attn2[tid] = a;

    out[b * HH + tid] = 0.f;
}

// ---------------------------------------------------------------------------
// K4: c_t[b][h] += sum_{s in chunk} attn[b,s] * eo[b,s,h]
// ---------------------------------------------------------------------------
#define K4_CHUNK 64
__global__ void __launch_bounds__(128) k_context(const float* __restrict__ eo,
                                                 float* __restrict__ out) {
    int b  = blockIdx.y;
    int s0 = blockIdx.x * K4_CHUNK;
    int t  = blockIdx.z * 128 + threadIdx.x;
    const float* attn = out + BB * HH + b * SS;
    const float4* eob = reinterpret_cast<const float4*>(eo + ((size_t)b * SS) * HH);

    float4 acc = make_float4(0.f, 0.f, 0.f, 0.f);
#pragma unroll 4
    for (int i = 0; i < K4_CHUNK; i++) {
        int s = s0 + i;
        float a  = __ldg(attn + s);
        float4 e = ldcs4(eob + (size_t)s * (HH / 4) + t);
        acc.x += a * e.x; acc.y += a * e.y;
        acc.z += a * e.z; acc.w += a * e.w;
    }
    float* ct = out + b * HH + t * 4;
    atomicAdd(ct + 0, acc.x);
    atomicAdd(ct + 1, acc.y);
    atomicAdd(ct + 2, acc.z);
    atomicAdd(ct + 3, acc.w);
}

// ---------------------------------------------------------------------------
extern "C" void kernel_launch(void* const* d_in, const int* in_sizes, int n_in,
                              void* d_out, int out_size) {
    const float* s_t_hat = (const float*)d_in[0];
    const float* enc_out = (const float*)d_in[1];
    const float* enc_fea = (const float*)d_in[2];
    const float* mask    = (const float*)d_in[3];
    const float* cov     = (const float*)d_in[4];
    const float* W_dec   = (const float*)d_in[5];
    const float* b_dec   = (const float*)d_in[6];
    const float* W_c     = (const float*)d_in[7];
    const float* v       = (const float*)d_in[8];
    float* out = (float*)d_out;

    float* scores = out + BB * HH + 2 * BB * SS;

    k_decproj<<<dim3(256, 4), 128>>>(s_t_hat, W_dec, b_dec, scores);
    k_scores<<<dim3(SS / SC_CHUNK, BB, 2), 128>>>(enc_fea, cov, W_c, v, scores);
    k_softmax<<<BB, 1024>>>(mask, out);
    k_context<<<dim3(SS / K4_CHUNK, BB, 2), 128>>>(enc_out, out);
}

// round 15
// speedup vs baseline: 1.0508x; 1.0245x over previous
#include <cuda_runtime.h>

#define BB 16
#define SS 4096
#define HH 1024

// scratch: per-segment partial dec_fea [4][B][H]
__device__ float g_part[4 * BB * HH];

__device__ __forceinline__ float tanh_fast(float x) {
    float y;
    asm("tanh.approx.f32 %0, %1;" : "=f"(y) : "f"(x));
    return y;
}

// streaming (evict-first) float4 load for zero-reuse tensors
__device__ __forceinline__ float4 ldcs4(const float4* p) {
    float4 r;
    asm("ld.global.cs.v4.f32 {%0,%1,%2,%3}, [%4];"
        : "=f"(r.x), "=f"(r.y), "=f"(r.z), "=f"(r.w) : "l"(p));
    return r;
}

__device__ __forceinline__ float warp_sum(float v) {
#pragma unroll
    for (int o = 16; o > 0; o >>= 1) v += __shfl_xor_sync(0xffffffffu, v, o);
    return v;
}

__device__ __forceinline__ float warp_max(float v) {
#pragma unroll
    for (int o = 16; o > 0; o >>= 1) v = fmaxf(v, __shfl_xor_sync(0xffffffffu, v, o));
    return v;
}

// ---------------------------------------------------------------------------
// K1: split-K decode projection, 4 segments of 256 floats.
// grid (256, 4) x 128 thr = 1024 blocks. Warp = (h, seg); merged butterfly-16
// reduction (5 SHFL). Even lane l writes batch (l>>1)&15. Bias in seg 0.
// Also zeroes the scores region for K2's atomics.
// ---------------------------------------------------------------------------
__global__ void k_decproj(const float* __restrict__ s_t,
                          const float* __restrict__ W,
                          const float* __restrict__ bias,
                          float* __restrict__ scores) {
    int gid = (blockIdx.x * 4 + blockIdx.y) * 128 + threadIdx.x;
    if (gid < 65536) scores[gid] = 0.f;

    int warp = threadIdx.x >> 5, lane = threadIdx.x & 31;
    int h   = blockIdx.x * 4 + warp;
    int seg = blockIdx.y;
    int k4a = seg * 64 + lane;
    int k4b = k4a + 32;

    const float4* Wrow = reinterpret_cast<const float4*>(W + (size_t)h * HH);
    float4 wa = __ldg(Wrow + k4a);
    float4 wb = __ldg(Wrow + k4b);

    float r[16];
#pragma unroll
    for (int b = 0; b < BB; b++) {
        const float4* sb = reinterpret_cast<const float4*>(s_t + b * HH);
        float4 sa = __ldg(sb + k4a);
        float4 s2 = __ldg(sb + k4b);
        r[b] = (wa.x * sa.x + wa.y * sa.y) + (wa.z * sa.z + wa.w * sa.w)
             + (wb.x * s2.x + wb.y * s2.y) + (wb.z * s2.z + wb.w * s2.w);
    }

    float m8[8];
#pragma unroll
    for (int i = 0; i < 8; i++) {
        bool hi = (lane & 16) != 0;
        float keep = hi ? r[i + 8] : r[i];
        float send = hi ? r[i] : r[i + 8];
        m8[i] = keep + __shfl_xor_sync(0xffffffffu, send, 16);
    }
    float m4[4];
#pragma unroll
    for (int i = 0; i < 4; i++) {
        bool hi = (lane & 8) != 0;
        float keep = hi ? m8[i + 4] : m8[i];
        float send = hi ? m8[i] : m8[i + 4];
        m4[i] = keep + __shfl_xor_sync(0xffffffffu, send, 8);
    }
    float m2[2];
#pragma unroll
    for (int i = 0; i < 2; i++) {
        bool hi = (lane & 4) != 0;
        float keep = hi ? m4[i + 2] : m4[i];
        float send = hi ? m4[i] : m4[i + 2];
        m2[i] = keep + __shfl_xor_sync(0xffffffffu, send, 4);
    }
    float m1;
    {
        bool hi = (lane & 2) != 0;
        float keep = hi ? m2[1] : m2[0];
        float send = hi ? m2[0] : m2[1];
        m1 = keep + __shfl_xor_sync(0xffffffffu, send, 2);
    }
    m1 += __shfl_xor_sync(0xffffffffu, m1, 1);

    if ((lane & 1) == 0) {
        int b = (lane >> 1) & 15;
        float bi = (seg == 0) ? __ldg(bias + h) : 0.f;
        g_part[(seg * BB + b) * HH + h] = m1 + bi;
    }
}

// ---------------------------------------------------------------------------
// K2: scores[b][s] += sum_{h in slice} tanh(ef + dec + cov*Wc) * v
// R11 shape: flat 8-row .cs LDG batch (MLP 8), merged butterflies + REDG.
// ---------------------------------------------------------------------------
#define SC_CHUNK 64

__device__ __forceinline__ void butterfly4_atomic(float a0, float a1, float a2,
                                                  float a3, int lane,
                                                  float* dst) {
    float x01 = (lane & 16) ? a1 : a0;
    float y01 = (lane & 16) ? a0 : a1;
    x01 += __shfl_xor_sync(0xffffffffu, y01, 16);
    float x23 = (lane & 16) ? a3 : a2;
    float y23 = (lane & 16) ? a2 : a3;
    x23 += __shfl_xor_sync(0xffffffffu, y23, 16);
    float m0 = (lane & 8) ? x23 : x01;
    float m1 = (lane & 8) ? x01 : x23;
    m0 += __shfl_xor_sync(0xffffffffu, m1, 8);
    m0 += __shfl_xor_sync(0xffffffffu, m0, 4);
    m0 += __shfl_xor_sync(0xffffffffu, m0, 2);
    m0 += __shfl_xor_sync(0xffffffffu, m0, 1);
    if ((lane & 7) == 0) {
        int r = ((lane >> 4) & 1) | ((lane >> 2) & 2);
        atomicAdd(dst + r, m0);
    }
}

__global__ void __launch_bounds__(128, 8) k_scores(const float* __restrict__ ef,
                                                   const float* __restrict__ cov,
                                                   const float* __restrict__ Wc,
                                                   const float* __restrict__ v,
                                                   float* __restrict__ scores) {
    int b  = blockIdx.y;
    int s0 = blockIdx.x * SC_CHUNK;
    int t  = blockIdx.z * 128 + threadIdx.x;
    int lane = threadIdx.x & 31;

    float4 p0 = __ldg(reinterpret_cast<const float4*>(g_part + (0 * BB + b) * HH) + t);
    float4 p1 = __ldg(reinterpret_cast<const float4*>(g_part + (1 * BB + b) * HH) + t);
    float4 p2 = __ldg(reinterpret_cast<const float4*>(g_part + (2 * BB + b) * HH) + t);
    float4 p3 = __ldg(reinterpret_cast<const float4*>(g_part + (3 * BB + b) * HH) + t);
    float4 d4;
    d4.x = (p0.x + p1.x) + (p2.x + p3.x);
    d4.y = (p0.y + p1.y) + (p2.y + p3.y);
    d4.z = (p0.z + p1.z) + (p2.z + p3.z);
    d4.w = (p0.w + p1.w) + (p2.w + p3.w);
    float4 w4 = __ldg(reinterpret_cast<const float4*>(Wc) + t);
    float4 v4 = __ldg(reinterpret_cast<const float4*>(v) + t);

    const float4* efb  = reinterpret_cast<const float4*>(ef + ((size_t)b * SS) * HH);
    const float4* cov4 = reinterpret_cast<const float4*>(cov + b * SS + s0);
    float* sc = scores + b * SS + s0;

#pragma unroll 1
    for (int g = 0; g < SC_CHUNK / 8; g++) {
        float4 f[8];
#pragma unroll
        for (int r = 0; r < 8; r++)
            f[r] = ldcs4(efb + (size_t)(s0 + g * 8 + r) * (HH / 4) + t);
        float4 c4a = __ldg(cov4 + g * 2);
        float4 c4b = __ldg(cov4 + g * 2 + 1);

        const float cr[8] = {c4a.x, c4a.y, c4a.z, c4a.w,
                             c4b.x, c4b.y, c4b.z, c4b.w};
        float acc[8];
#pragma unroll
        for (int r = 0; r < 8; r++) {
            float c = cr[r];
            float e0 = tanh_fast(f[r].x + fmaf(c, w4.x, d4.x));
            float e1 = tanh_fast(f[r].y + fmaf(c, w4.y, d4.y));
            float e2 = tanh_fast(f[r].z + fmaf(c, w4.z, d4.z));
            float e3 = tanh_fast(f[r].w + fmaf(c, w4.w, d4.w));
            acc[r] = fmaf(e0, v4.x, fmaf(e1, v4.y, fmaf(e2, v4.z, e3 * v4.w)));
        }
        butterfly4_atomic(acc[0], acc[1], acc[2], acc[3], lane, sc + g * 8);
        butterfly4_atomic(acc[4], acc[5], acc[6], acc[7], lane, sc + g * 8 + 4);
    }
}

// ---------------------------------------------------------------------------
// K3: masked softmax + renorm, 4 blocks per batch (grid BB x 4, 256 thr).
// Each block redundantly computes its batch's stats (scores L2-hot), then
// writes ONLY its quarter of attn1/attn2 and zeroes its quarter of c_t.
// Thread tid's k=q register holds exactly output float4 q*256+tid.
// ---------------------------------------------------------------------------
__global__ void __launch_bounds__(256) k_softmax(const float* __restrict__ mask,
                                                 float* __restrict__ out) {
    int b   = blockIdx.x;
    int q   = blockIdx.y;
    int tid = threadIdx.x;
    int warp = tid >> 5, lane = tid & 31;

    const float4* scb = reinterpret_cast<const float4*>(out + BB * HH + 2 * BB * SS + b * SS);
    const float4* mb  = reinterpret_cast<const float4*>(mask + b * SS);

    __shared__ float red[8];

    // load all 1024 float4 scores of this batch: thread tid holds k=0..3
    float4 sv[4];
#pragma unroll
    for (int k = 0; k < 4; k++) sv[k] = __ldg(scb + tid + k * 256);

    // block max
    float mx = -3.402823466e+38f;
#pragma unroll
    for (int k = 0; k < 4; k++)
        mx = fmaxf(mx, fmaxf(fmaxf(sv[k].x, sv[k].y), fmaxf(sv[k].z, sv[k].w)));
    mx = warp_max(mx);
    if (lane == 0) red[warp] = mx;
    __syncthreads();
    if (tid == 0) {
        float t = red[0];
#pragma unroll
        for (int i = 1; i < 8; i++) t = fmaxf(t, red[i]);
        red[0] = t;
    }
    __syncthreads();
    mx = red[0];
    __syncthreads();

    // exp + block sum
    float lsum = 0.f;
#pragma unroll
    for (int k = 0; k < 4; k++) {
        sv[k].x = __expf(sv[k].x - mx); sv[k].y = __expf(sv[k].y - mx);
        sv[k].z = __expf(sv[k].z - mx); sv[k].w = __expf(sv[k].w - mx);
        lsum += (sv[k].x + sv[k].y) + (sv[k].z + sv[k].w);
    }
    lsum = warp_sum(lsum);
    if (lane == 0) red[warp] = lsum;
    __syncthreads();
    if (tid == 0) {
        float t = 0.f;
#pragma unroll
        for (int i = 0; i < 8; i++) t += red[i];
        red[0] = t;
    }
    __syncthreads();
    float inv = 1.f / red[0];
    __syncthreads();

    // masked sum
    float4 mk[4];
    float lms = 0.f;
#pragma unroll
    for (int k = 0; k < 4; k++) {
        mk[k] = __ldg(mb + tid + k * 256);
        lms += (sv[k].x * mk[k].x + sv[k].y * mk[k].y)
             + (sv[k].z * mk[k].z + sv[k].w * mk[k].w);
    }
    lms = warp_sum(lms);
    if (lane == 0) red[warp] = lms;
    __syncthreads();
    if (tid == 0) {
        float t = 0.f;
#pragma unroll
        for (int i = 0; i < 8; i++) t += red[i];
        red[0] = t;
    }
    __syncthreads();
    float inv2 = 1.f / (red[0] * inv + 1e-20f);
    float scale = inv * inv2;

    // write quarter q of attn1/attn2 (thread's k=q lane IS float4 q*256+tid)
    float4 a;
    a.x = sv[q].x * mk[q].x * scale; a.y = sv[q].y * mk[q].y * scale;
    a.z = sv[q].z * mk[q].z * scale; a.w = sv[q].w * mk[q].w * scale;
    int o4 = q * 256 + tid;
    reinterpret_cast<float4*>(out + BB * HH + b * SS)[o4] = a;
    reinterpret_cast<float4*>(out + BB * HH + BB * SS + b * SS)[o4] = a;

    // zero quarter q of c_t[b]
    out[b * HH + q * 256 + tid] = 0.f;
}

// ---------------------------------------------------------------------------
// K4: c_t[b][h] += sum_{s in chunk} attn[b,s] * eo[b,s,h]
// ---------------------------------------------------------------------------
#define K4_CHUNK 64
__global__ void __launch_bounds__(128) k_context(const float* __restrict__ eo,
                                                 float* __restrict__ out) {
    int b  = blockIdx.y;
    int s0 = blockIdx.x * K4_CHUNK;
    int t  = blockIdx.z * 128 + threadIdx.x;
    const float* attn = out + BB * HH + b * SS;
    const float4* eob = reinterpret_cast<const float4*>(eo + ((size_t)b * SS) * HH);

    float4 acc = make_float4(0.f, 0.f, 0.f, 0.f);
#pragma unroll 4
    for (int i = 0; i < K4_CHUNK; i++) {
        int s = s0 + i;
        float a  = __ldg(attn + s);
        float4 e = ldcs4(eob + (size_t)s * (HH / 4) + t);
        acc.x += a * e.x; acc.y += a * e.y;
        acc.z += a * e.z; acc.w += a * e.w;
    }
    float* ct = out + b * HH + t * 4;
    atomicAdd(ct + 0, acc.x);
    atomicAdd(ct + 1, acc.y);
    atomicAdd(ct + 2, acc.z);
    atomicAdd(ct + 3, acc.w);
}

// ---------------------------------------------------------------------------
extern "C" void kernel_launch(void* const* d_in, const int* in_sizes, int n_in,
                              void* d_out, int out_size) {
    const float* s_t_hat = (const float*)d_in[0];
    const float* enc_out = (const float*)d_in[1];
    const float* enc_fea = (const float*)d_in[2];
    const float* mask    = (const float*)d_in[3];
    const float* cov     = (const float*)d_in[4];
    const float* W_dec   = (const float*)d_in[5];
    const float* b_dec   = (const float*)d_in[6];
    const float* W_c     = (const float*)d_in[7];
    const float* v       = (const float*)d_in[8];
    float* out = (float*)d_out;

    float* scores = out + BB * HH + 2 * BB * SS;

    k_decproj<<<dim3(256, 4), 128>>>(s_t_hat, W_dec, b_dec, scores);
    k_scores<<<dim3(SS / SC_CHUNK, BB, 2), 128>>>(enc_fea, cov, W_c, v, scores);
    k_softmax<<<dim3(BB, 4), 256>>>(mask, out);
    k_context<<<dim3(SS / K4_CHUNK, BB, 2), 128>>>(enc_out, out);
}